// round 15
// baseline (speedup 1.0000x reference)
#include <cuda_runtime.h>

// ---------------- scratch (device globals; no allocation allowed) ----------------
__device__ float g_A1[221184];    // layer1 eff weights, k-major: [kk(96)][ojcol(2304)=oj*16+n]
__device__ float g_A2[688128];    // layer2 eff weights: [j][kk(384)][col(256)] (BN1-scaled in place)
__device__ float g_t1[4718592];   // transposed: [kidx(1152)=c*72+j*8+n][b(4096)]
__device__ float g_t2[3670016];   // transposed: [idx(896)=c*28+j*4+l][b(4096)]
__device__ float g_t3[1310720];   // transposed: [idx(320)=o*5+j][b(4096)]
__device__ float g_red[224];      // sum1[16] ssq1[16] sum2[32] ssq2[32] sum3[64] ssq3[64]
__device__ float g_bn1[32];       // [scale16][shift16]
__device__ float g_bn2[64];       // [scale32][shift32]
__device__ float g_bn3[128];      // [scale64][shift64]
__device__ float g_bias2[1792];   // [j(7)][col(256)]  BN1-shift folded through A2
__device__ float g_w3f[6144];     // [kidx(96)=c*3+rr][o3(64)]  BN2-scale folded
__device__ float g_bias3[64];     // BN2-shift folded through w3
__device__ float g_fw1f[5120];    // transposed [k(320)][o(16)], BN3-scale folded
__device__ float g_fb1f[16];      // BN3-shift folded

typedef unsigned long long ull;

__device__ __forceinline__ void fma2(ull& d, ull a, ull b) {
    asm("fma.rn.f32x2 %0, %1, %2, %0;" : "+l"(d) : "l"(a), "l"(b));
}
__device__ __forceinline__ ull dup2(float v) {
    ull r;
    asm("mov.b64 %0, {%1, %1};" : "=l"(r) : "f"(v));
    return r;
}
__device__ __forceinline__ float warp_sum(float v) {
    #pragma unroll
    for (int o = 16; o; o >>= 1) v += __shfl_down_sync(0xffffffffu, v, o);
    return v;
}

// Combined prep: zero reductions/bias2, build A1 (k-major) and A2 (fp32).
__global__ void k_prep(const float* __restrict__ w1, const float* __restrict__ w2) {
    int id = blockIdx.x * blockDim.x + threadIdx.x;
    if (id < 224) g_red[id] = 0.f;
    if (id < 1792) g_bias2[id] = 0.f;
    if (id < 221184) {
        int n  = id & 15;
        int kk = (id >> 4) % 96;
        int oj = id / 1536;
        int o = oj / 9, j = oj % 9;
        int c = kk >> 4, p = kk & 15;
        int h = 1 << j;
        int d = p - n;
        float v = 0.f;
        if (d >= -3 * h && d <= 3 * h) {
            float t = (float)d / (float)h;
            #pragma unroll
            for (int mm = 0; mm < 7; mm++) {
                float hat = 1.f - fabsf(t - (float)(mm - 3));
                if (hat > 0.f) v += w1[(o * 6 + c) * 7 + mm] * hat;
            }
            v /= (float)h;
        }
        g_A1[kk * 2304 + oj * 16 + n] = v;
    }
    if (id < 688128) {
        int col = id & 255;
        int kk  = (id >> 8) % 384;
        int j   = id / 98304;
        int o = col >> 3, n = col & 7;
        int p = kk & 7;
        int cr = kk >> 3;               // c*3+r
        int h = 1 << j;
        int d = p - n;
        float v = 0.f;
        if (d >= -h && d <= h) {
            float t = (float)d / (float)h;
            #pragma unroll
            for (int mm = 0; mm < 3; mm++) {
                float hat = 1.f - fabsf(t - (float)(mm - 1));
                if (hat > 0.f) v += w2[(o * 48 + cr) * 3 + mm] * hat;
            }
            v /= (float)h;
        }
        g_A2[id] = v;
    }
}

// ---------------------------------------------------------------------------
// Layer1: C[4096 x 2304] = X[4096 x 96] * A1[96 x 2304], fused pool+relu+stats.
// Block 128 rows x 128 cols (8 oj groups), 256 threads, col-pair FMA2.
// smem: aT[96][129]=12384 | wT[96][132]=12672 floats => 100224 B. 2 blk/SM.
// ---------------------------------------------------------------------------
__global__ void __launch_bounds__(256, 2) k_layer1(const float* __restrict__ x) {
    extern __shared__ float sm[];
    float* aT = sm;               // [96][129]
    float* wT = sm + 12384;       // [96][132]
    const int t = threadIdx.x;
    const int b0  = blockIdx.x * 128;
    const int oj0 = blockIdx.y * 8;
    const int rg = t & 15, cg = t >> 4;

    // stage X transposed (scalar: LDG coalesced, STS stride-129 conflict-free)
    for (int i = t; i < 12288; i += 256) {
        int r = i / 96, kk = i - r * 96;
        aT[kk * 129 + r] = x[(b0 + r) * 96 + kk];
    }
    // stage W vectorized (A1 k-major, contiguous 128 floats per kk)
    for (int i = t; i < 3072; i += 256) {
        int kk = i >> 5, c4 = (i & 31) * 4;
        float4 v = *reinterpret_cast<const float4*>(g_A1 + kk * 2304 + oj0 * 16 + c4);
        *reinterpret_cast<float4*>(wT + kk * 132 + c4) = v;
    }
    __syncthreads();

    ull acc[8][4];
    #pragma unroll
    for (int i = 0; i < 8; i++)
        #pragma unroll
        for (int p = 0; p < 4; p++) acc[i][p] = 0ull;

    const float* pa = aT + rg;
    const float* pw = wT + 8 * cg;
    #pragma unroll 2
    for (int k = 0; k < 96; k++) {
        ull wv[4];
        #pragma unroll
        for (int p = 0; p < 4; p++)
            wv[p] = *reinterpret_cast<const ull*>(pw + k * 132 + 2 * p);
        ull ad[8];
        #pragma unroll
        for (int i = 0; i < 8; i++) ad[i] = dup2(pa[k * 129 + 16 * i]);
        #pragma unroll
        for (int i = 0; i < 8; i++)
            #pragma unroll
            for (int p = 0; p < 4; p++) fma2(acc[i][p], ad[i], wv[p]);
    }
    __syncthreads();

    // pre[128][130] reuses smem
    float* pre = sm;
    #pragma unroll
    for (int i = 0; i < 8; i++)
        #pragma unroll
        for (int p = 0; p < 4; p++)
            *reinterpret_cast<float2*>(pre + (rg + 16 * i) * 130 + 8 * cg + 2 * p) =
                *reinterpret_cast<float2*>(&acc[i][p]);
    __syncthreads();

    // Pool(4,s2,p1)+relu+stats. thread = (row, half) -> 4 oj groups. Stores to
    // transposed g_t1[kidx][b] (coalesced across row-threads).
    const int row = t & 127, half = t >> 7;
    const float* pr = pre + row * 130;
    #pragma unroll
    for (int gg = 0; gg < 4; gg++) {
        int g = half * 4 + gg;
        int oj = oj0 + g;
        int o = oj / 9, jj = oj - o * 9;
        float* dst = g_t1 + (long)(o * 72 + jj * 8) * 4096 + b0 + row;
        float s = 0.f, ss = 0.f;
        #pragma unroll
        for (int k = 0; k < 8; k++) {
            int lo = (2 * k - 1 < 0) ? 0 : 2 * k - 1;
            int hi = (2 * k + 2 > 15) ? 15 : 2 * k + 2;
            float m = pr[g * 16 + lo];
            for (int nn = lo + 1; nn <= hi; nn++) m = fmaxf(m, pr[g * 16 + nn]);
            m = fmaxf(m, 0.f);
            dst[k * 4096] = m;
            s += m; ss += m * m;
        }
        float sA = warp_sum(s), ssA = warp_sum(ss);
        if ((t & 31) == 0) {
            atomicAdd(&g_red[o], sA);
            atomicAdd(&g_red[16 + o], ssA);
        }
    }
}

// BN params for layer1 only.
__global__ void k_bn1(const float* __restrict__ g, const float* __restrict__ b) {
    int c = threadIdx.x;
    if (c >= 16) return;
    float sum = g_red[c], ssq = g_red[16 + c];
    float mean = sum / 294912.f;
    float var = ssq / 294912.f - mean * mean;
    float sc = g[c] * rsqrtf(var + 2e-5f);
    g_bn1[c] = sc;
    g_bn1[16 + c] = b[c] - mean * sc;
}

// Fused: bias2 accumulation (from unscaled A2) + in-place BN1 scaling of A2.
// Thread handles one (j, col, group of 48 kk); one atomicAdd per thread.
__global__ void k_biasscale2() {
    int id = blockIdx.x * blockDim.x + threadIdx.x;
    if (id >= 14336) return;
    int j = id >> 11, rem = id & 2047;
    int col = rem & 255, gg = rem >> 8;          // gg 0..7 -> kk gg*48..+47, c = 2gg, 2gg+1
    float sc0 = g_bn1[2 * gg],     sh0 = g_bn1[16 + 2 * gg];
    float sc1 = g_bn1[2 * gg + 1], sh1 = g_bn1[16 + 2 * gg + 1];
    float* base = g_A2 + (long)j * 98304 + (long)gg * 48 * 256 + col;
    float s = 0.f;
    #pragma unroll 4
    for (int kkl = 0; kkl < 24; kkl++) {
        float v = base[kkl * 256];
        s += sh0 * v;
        base[kkl * 256] = v * sc0;
    }
    #pragma unroll 4
    for (int kkl = 24; kkl < 48; kkl++) {
        float v = base[kkl * 256];
        s += sh1 * v;
        base[kkl * 256] = v * sc1;
    }
    atomicAdd(&g_bias2[j * 256 + col], s);
}

// ---------------------------------------------------------------------------
// Layer2: per j: C[4096 x 256] = acts[4096 x 384] * A2'[j] + bias2[j],
// fused pool+relu+stats. BN1 pre-folded -> staging pure vectorized copies.
// Block 128 rows x 128 cols, 256 thr, col-pair FMA2. K in 6 tiles of 64.
// smem 67584 B -> 3 blocks/SM (24 warps).
// ---------------------------------------------------------------------------
__global__ void __launch_bounds__(256, 3) k_layer2() {
    extern __shared__ float sm[];
    float* aT = sm;               // [64][132]
    float* wT = sm + 8448;        // [64][132]
    const int t = threadIdx.x;
    const int b0 = blockIdx.x * 128;
    const int cb = blockIdx.y;    // col block: o2 channels cb*16..+15
    const int j  = blockIdx.z;
    const int rg = t & 15, cg = t >> 4;

    ull acc[8][4];
    #pragma unroll
    for (int i = 0; i < 8; i++)
        #pragma unroll
        for (int p = 0; p < 4; p++) acc[i][p] = 0ull;

    const float* wbase = g_A2 + j * 98304 + cb * 128;

    for (int kt = 0; kt < 6; kt++) {
        __syncthreads();
        // acts tile: pure float4 copy from transposed g_t1
        for (int i = t; i < 2048; i += 256) {
            int kk = i >> 5, r4 = (i & 31) * 4;
            int k = kt * 64 + kk;
            int c = k / 24, rem = k - c * 24;
            float4 v = *reinterpret_cast<const float4*>(
                g_t1 + (long)(c * 72 + j * 8 + rem) * 4096 + b0 + r4);
            *reinterpret_cast<float4*>(aT + kk * 132 + r4) = v;
        }
        // weight tile: float4 copy
        for (int i = t; i < 2048; i += 256) {
            int kk = i >> 5, c4 = (i & 31) * 4;
            float4 v = *reinterpret_cast<const float4*>(wbase + (kt * 64 + kk) * 256 + c4);
            *reinterpret_cast<float4*>(wT + kk * 132 + c4) = v;
        }
        __syncthreads();

        const float* pa = aT + rg;
        const float* pw = wT + 8 * cg;
        #pragma unroll 2
        for (int k = 0; k < 64; k++) {
            ull wv[4];
            #pragma unroll
            for (int p = 0; p < 4; p++)
                wv[p] = *reinterpret_cast<const ull*>(pw + k * 132 + 2 * p);
            ull ad[8];
            #pragma unroll
            for (int i = 0; i < 8; i++) ad[i] = dup2(pa[k * 132 + 16 * i]);
            #pragma unroll
            for (int i = 0; i < 8; i++)
                #pragma unroll
                for (int p = 0; p < 4; p++) fma2(acc[i][p], ad[i], wv[p]);
        }
    }
    __syncthreads();

    // add bias2 and spill to pre[128][130]
    float* pre = sm;
    {
        const float* bb = g_bias2 + j * 256 + cb * 128 + 8 * cg;
        float2 bv[4];
        #pragma unroll
        for (int p = 0; p < 4; p++) bv[p] = *reinterpret_cast<const float2*>(bb + 2 * p);
        __syncthreads();
        #pragma unroll
        for (int i = 0; i < 8; i++)
            #pragma unroll
            for (int p = 0; p < 4; p++) {
                float2 v = *reinterpret_cast<float2*>(&acc[i][p]);
                v.x += bv[p].x; v.y += bv[p].y;
                *reinterpret_cast<float2*>(pre + (rg + 16 * i) * 130 + 8 * cg + 2 * p) = v;
            }
    }
    __syncthreads();

    // Pool(4,s2,p1)+relu+stats -> transposed g_t2[idx][b]
    const int row = t & 127, half = t >> 7;
    const float* pr = pre + row * 130;
    #pragma unroll
    for (int ol = 0; ol < 8; ol++) {
        int lc = half * 8 + ol;
        int o2g = cb * 16 + lc;
        float* dst = g_t2 + (long)(o2g * 28 + j * 4) * 4096 + b0 + row;
        float s = 0.f, ss = 0.f;
        #pragma unroll
        for (int k = 0; k < 4; k++) {
            int lo = (2 * k - 1 < 0) ? 0 : 2 * k - 1;
            int hi = (2 * k + 2 > 7) ? 7 : 2 * k + 2;
            float m = pr[lc * 8 + lo];
            for (int nn = lo + 1; nn <= hi; nn++) m = fmaxf(m, pr[lc * 8 + nn]);
            m = fmaxf(m, 0.f);
            dst[k * 4096] = m;
            s += m; ss += m * m;
        }
        float sA = warp_sum(s), ssA = warp_sum(ss);
        if ((t & 31) == 0) {
            atomicAdd(&g_red[32 + o2g], sA);
            atomicAdd(&g_red[64 + o2g], ssA);
        }
    }
}

// Fused: BN2 params + fold into w3 (g_w3f) and bias3. Single block.
__global__ void k_bnfold2(const float* __restrict__ g, const float* __restrict__ b,
                          const float* __restrict__ w3) {
    int t = threadIdx.x;
    if (t < 32) {
        float sum = g_red[32 + t], ssq = g_red[64 + t];
        float mean = sum / 114688.f;
        float var = ssq / 114688.f - mean * mean;
        float sc = g[t] * rsqrtf(var + 2e-5f);
        g_bn2[t] = sc;
        g_bn2[32 + t] = b[t] - mean * sc;
    }
    __syncthreads();
    for (int i = t; i < 6144; i += 256) {
        int kidx = i >> 6, o = i & 63;
        int c = kidx / 3, rr = kidx - c * 3;
        g_w3f[i] = w3[(o * 32 + c) * 3 + rr] * g_bn2[c];
    }
    if (t < 64) {
        float s = 0.f;
        for (int c = 0; c < 32; c++)
            s += (w3[(t * 32 + c) * 3] + w3[(t * 32 + c) * 3 + 1] + w3[(t * 32 + c) * 3 + 2])
                 * g_bn2[32 + c];
        g_bias3[t] = s;
    }
}

// ---------------------------------------------------------------------------
// Layer3: per batch-tile of 16 rows, f32x2 row-pair. smem 96256 B, 2 blk/SM.
// ---------------------------------------------------------------------------
__global__ void __launch_bounds__(256, 2) k_layer3() {
    extern __shared__ float sm[];
    float* actsT = sm;             // [896][20]
    float* ws    = sm + 17920;     // [96][64]
    __shared__ float st[128];
    const int t = threadIdx.x;
    const int b0 = blockIdx.x * 16;

    for (int i = t; i < 3584; i += 256) {
        int idx = i >> 2, r4 = (i & 3) * 4;
        float4 v = *reinterpret_cast<const float4*>(g_t2 + (long)idx * 4096 + b0 + r4);
        *reinterpret_cast<float4*>(actsT + idx * 20 + r4) = v;
    }
    for (int i = t; i < 6144; i += 256) ws[i] = g_w3f[i];
    if (t < 128) st[t] = 0.f;
    __syncthreads();

    const int o3 = t & 63, rpg = t >> 6;
    const ull* a64 = reinterpret_cast<const ull*>(actsT);  // stride 10 per idx
    const float invj[5] = {1.f, 0.5f, 0.25f, 0.125f, 0.0625f};
    const float bias = g_bias3[o3];
    float s = 0.f, ssq = 0.f;

    #pragma unroll
    for (int hf = 0; hf < 2; hf++) {
        const int rp = rpg + 4 * hf;
        ull accp[15];
        #pragma unroll
        for (int i = 0; i < 15; i++) accp[i] = 0ull;

        for (int c = 0; c < 32; c++) {
            ull av[21];
            #pragma unroll
            for (int m = 0; m < 7; m++)
                #pragma unroll
                for (int l = 0; l < 3; l++)
                    av[m * 3 + l] = a64[(c * 28 + m * 4 + l) * 10 + rp];
            ull w0 = dup2(ws[(c * 3 + 0) * 64 + o3]);
            ull w1 = dup2(ws[(c * 3 + 1) * 64 + o3]);
            ull w2 = dup2(ws[(c * 3 + 2) * 64 + o3]);
            #pragma unroll
            for (int jj = 0; jj < 5; jj++)
                #pragma unroll
                for (int l = 0; l < 3; l++) {
                    fma2(accp[jj * 3 + l], w0, av[(jj + 0) * 3 + l]);
                    fma2(accp[jj * 3 + l], w1, av[(jj + 1) * 3 + l]);
                    fma2(accp[jj * 3 + l], w2, av[(jj + 2) * 3 + l]);
                }
        }
        #pragma unroll
        for (int jj = 0; jj < 5; jj++) {
            float2 v0 = *reinterpret_cast<float2*>(&accp[jj * 3 + 0]);
            float2 v1 = *reinterpret_cast<float2*>(&accp[jj * 3 + 1]);
            float2 v2 = *reinterpret_cast<float2*>(&accp[jj * 3 + 2]);
            float mx = (fmaxf(fmaxf(v0.x, v1.x), v2.x) + bias) * invj[jj];
            float my = (fmaxf(fmaxf(v0.y, v1.y), v2.y) + bias) * invj[jj];
            mx = fmaxf(mx, 0.f); my = fmaxf(my, 0.f);
            *reinterpret_cast<float2*>(g_t3 + (long)(o3 * 5 + jj) * 4096 + b0 + 2 * rp) =
                make_float2(mx, my);
            s += mx + my; ssq += mx * mx + my * my;
        }
    }
    atomicAdd(&st[o3], s);
    atomicAdd(&st[64 + o3], ssq);
    __syncthreads();
    if (t < 64) { atomicAdd(&g_red[96 + t], st[t]); atomicAdd(&g_red[160 + t], st[64 + t]); }
}

// Fused: BN3 params + fold into fw1 (g_fw1f/g_fb1f). Single block.
__global__ void k_bnfold3(const float* __restrict__ g, const float* __restrict__ b,
                          const float* __restrict__ fw1, const float* __restrict__ fb1) {
    int t = threadIdx.x;
    if (t < 64) {
        float sum = g_red[96 + t], ssq = g_red[160 + t];
        float mean = sum / 20480.f;
        float var = ssq / 20480.f - mean * mean;
        float sc = g[t] * rsqrtf(var + 2e-5f);
        g_bn3[t] = sc;
        g_bn3[64 + t] = b[t] - mean * sc;
    }
    __syncthreads();
    for (int i = t; i < 5120; i += 256) {
        int o = i / 320, k = i - o * 320;
        g_fw1f[k * 16 + o] = fw1[i] * g_bn3[k / 5];
    }
    if (t < 16) {
        float s = fb1[t];
        for (int k = 0; k < 320; k++)
            s += fw1[t * 320 + k] * g_bn3[64 + k / 5];
        g_fb1f[t] = s;
    }
}

// 3-layer MLP; BN3 prefolded into g_fw1f/g_fb1f; t3 transposed staging.
__global__ void __launch_bounds__(128) k_fc(const float* __restrict__ fw2, const float* __restrict__ fb2,
                                            const float* __restrict__ fw3, const float* __restrict__ fb3,
                                            float* __restrict__ out) {
    __shared__ float w1s[5120];            // [k][o]
    __shared__ float vtT[32 * 132];        // [c2][row]
    __shared__ float w2s[256];
    __shared__ float w3s[272];
    __shared__ float b1s[16], b2s[16], b3s[17];
    int t = threadIdx.x;
    int bbase = blockIdx.x * 128;
    for (int i = t; i < 5120; i += 128) w1s[i] = g_fw1f[i];
    for (int i = t; i < 256; i += 128) w2s[i] = fw2[i];
    for (int i = t; i < 272; i += 128) w3s[i] = fw3[i];
    if (t < 16) { b1s[t] = g_fb1f[t]; b2s[t] = fb2[t]; }
    if (t < 17) b3s[t] = fb3[t];
    __syncthreads();

    float h1[16];
    #pragma unroll
    for (int o = 0; o < 16; o++) h1[o] = b1s[o];

    for (int i0 = 0; i0 < 320; i0 += 32) {
        __syncthreads();
        for (int i = t; i < 1024; i += 128) {
            int c2 = i >> 5, r4 = (i & 31) * 4;
            float4 v = *reinterpret_cast<const float4*>(g_t3 + (long)(i0 + c2) * 4096 + bbase + r4);
            *reinterpret_cast<float4*>(vtT + c2 * 132 + r4) = v;
        }
        __syncthreads();
        #pragma unroll 4
        for (int c2 = 0; c2 < 32; c2++) {
            float v = vtT[c2 * 132 + t];
            const float* wr = &w1s[(i0 + c2) * 16];
            #pragma unroll
            for (int o = 0; o < 16; o++) h1[o] += v * wr[o];
        }
    }
    float h2[16];
    #pragma unroll
    for (int o = 0; o < 16; o++) {
        float a = b2s[o];
        #pragma unroll
        for (int k = 0; k < 16; k++) a += h1[k] * w2s[o * 16 + k];
        h2[o] = a;
    }
    int b = bbase + t;
    #pragma unroll
    for (int o = 0; o < 17; o++) {
        float a = b3s[o];
        #pragma unroll
        for (int k = 0; k < 16; k++) a += h2[k] * w3s[o * 16 + k];
        out[b * 17 + o] = a;
    }
}

extern "C" void kernel_launch(void* const* d_in, const int* in_sizes, int n_in,
                              void* d_out, int out_size) {
    const float* x   = (const float*)d_in[0];
    const float* w1  = (const float*)d_in[1];
    const float* w2  = (const float*)d_in[2];
    const float* w3  = (const float*)d_in[3];
    const float* g1  = (const float*)d_in[4];
    const float* b1  = (const float*)d_in[5];
    const float* g2  = (const float*)d_in[6];
    const float* b2  = (const float*)d_in[7];
    const float* g3  = (const float*)d_in[8];
    const float* b3  = (const float*)d_in[9];
    const float* fw1 = (const float*)d_in[10];
    const float* fb1 = (const float*)d_in[11];
    const float* fw2 = (const float*)d_in[12];
    const float* fb2 = (const float*)d_in[13];
    const float* fw3 = (const float*)d_in[14];
    const float* fb3 = (const float*)d_in[15];
    float* out = (float*)d_out;

    cudaFuncSetAttribute(k_layer1, cudaFuncAttributeMaxDynamicSharedMemorySize, 100224);
    cudaFuncSetAttribute(k_layer2, cudaFuncAttributeMaxDynamicSharedMemorySize, 67584);
    cudaFuncSetAttribute(k_layer3, cudaFuncAttributeMaxDynamicSharedMemorySize, 96256);

    k_prep<<<2688, 256>>>(w1, w2);
    k_layer1<<<dim3(32, 18), 256, 100224>>>(x);
    k_bn1<<<1, 32>>>(g1, b1);
    k_biasscale2<<<56, 256>>>();
    k_layer2<<<dim3(32, 2, 7), 256, 67584>>>();
    k_bnfold2<<<1, 256>>>(g2, b2, w3);
    k_layer3<<<256, 256, 96256>>>();
    k_bnfold3<<<1, 256>>>(g3, b3, fw1, fb1);
    k_fc<<<32, 128>>>(fw2, fb2, fw3, fb3, out);
}

// round 16
// speedup vs baseline: 1.9911x; 1.9911x over previous
#include <cuda_runtime.h>

// ---------------- scratch (device globals; no allocation allowed) ----------------
__device__ float g_A1[221184];    // layer1 eff weights, k-major: [kk(96)][ojcol(2304)=oj*16+n]
__device__ float g_A2[688128];    // layer2 eff weights: [j][kk(384)][col(256)] (BN1-scaled in place)
__device__ float g_t1[4718592];   // transposed: [kidx(1152)=c*72+j*8+n][b(4096)]
__device__ float g_t2[3670016];   // transposed: [idx(896)=c*28+j*4+l][b(4096)]
__device__ float g_t3[1310720];   // transposed: [idx(320)=o*5+j][b(4096)]
__device__ float g_red[224];      // sum1[16] ssq1[16] sum2[32] ssq2[32] sum3[64] ssq3[64]
__device__ float g_bn1[32];       // [scale16][shift16]
__device__ float g_bn2[64];       // [scale32][shift32]
__device__ float g_bn3[128];      // [scale64][shift64]
__device__ float g_bias2[1792];   // [j(7)][col(256)]  BN1-shift folded through A2
__device__ float g_w3f[6144];     // [kidx(96)=c*3+rr][o3(64)]  BN2-scale folded
__device__ float g_bias3[64];     // BN2-shift folded through w3
__device__ float g_fw1f[5120];    // transposed [k(320)][o(16)], BN3-scale folded
__device__ float g_fb1f[16];      // BN3-shift folded

typedef unsigned long long ull;

__device__ __forceinline__ void fma2(ull& d, ull a, ull b) {
    asm("fma.rn.f32x2 %0, %1, %2, %0;" : "+l"(d) : "l"(a), "l"(b));
}
__device__ __forceinline__ ull dup2(float v) {
    ull r;
    asm("mov.b64 %0, {%1, %1};" : "=l"(r) : "f"(v));
    return r;
}
__device__ __forceinline__ float warp_sum(float v) {
    #pragma unroll
    for (int o = 16; o; o >>= 1) v += __shfl_down_sync(0xffffffffu, v, o);
    return v;
}

// Combined prep: zero reductions/bias2, build A1 (k-major) and A2 (fp32).
__global__ void k_prep(const float* __restrict__ w1, const float* __restrict__ w2) {
    int id = blockIdx.x * blockDim.x + threadIdx.x;
    if (id < 224) g_red[id] = 0.f;
    if (id < 1792) g_bias2[id] = 0.f;
    if (id < 221184) {
        int n  = id & 15;
        int kk = (id >> 4) % 96;
        int oj = id / 1536;
        int o = oj / 9, j = oj % 9;
        int c = kk >> 4, p = kk & 15;
        int h = 1 << j;
        int d = p - n;
        float v = 0.f;
        if (d >= -3 * h && d <= 3 * h) {
            float t = (float)d / (float)h;
            #pragma unroll
            for (int mm = 0; mm < 7; mm++) {
                float hat = 1.f - fabsf(t - (float)(mm - 3));
                if (hat > 0.f) v += w1[(o * 6 + c) * 7 + mm] * hat;
            }
            v /= (float)h;
        }
        g_A1[kk * 2304 + oj * 16 + n] = v;
    }
    if (id < 688128) {
        int col = id & 255;
        int kk  = (id >> 8) % 384;
        int j   = id / 98304;
        int o = col >> 3, n = col & 7;
        int p = kk & 7;
        int cr = kk >> 3;               // c*3+r
        int h = 1 << j;
        int d = p - n;
        float v = 0.f;
        if (d >= -h && d <= h) {
            float t = (float)d / (float)h;
            #pragma unroll
            for (int mm = 0; mm < 3; mm++) {
                float hat = 1.f - fabsf(t - (float)(mm - 1));
                if (hat > 0.f) v += w2[(o * 48 + cr) * 3 + mm] * hat;
            }
            v /= (float)h;
        }
        g_A2[id] = v;
    }
}

// ---------------------------------------------------------------------------
// Layer1: C[4096 x 2304] = X[4096 x 96] * A1[96 x 2304], fused pool+relu+stats.
// Block 128 rows x 128 cols (8 oj groups), 256 threads, col-pair FMA2.
// smem: aT[96][129]=12384 | wT[96][132]=12672 floats => 100224 B. 2 blk/SM.
// ---------------------------------------------------------------------------
__global__ void __launch_bounds__(256, 2) k_layer1(const float* __restrict__ x) {
    extern __shared__ float sm[];
    float* aT = sm;               // [96][129]
    float* wT = sm + 12384;       // [96][132]
    const int t = threadIdx.x;
    const int b0  = blockIdx.x * 128;
    const int oj0 = blockIdx.y * 8;
    const int rg = t & 15, cg = t >> 4;

    // stage X transposed (scalar: LDG coalesced, STS stride-129 conflict-free)
    for (int i = t; i < 12288; i += 256) {
        int r = i / 96, kk = i - r * 96;
        aT[kk * 129 + r] = x[(b0 + r) * 96 + kk];
    }
    // stage W vectorized (A1 k-major, contiguous 128 floats per kk)
    for (int i = t; i < 3072; i += 256) {
        int kk = i >> 5, c4 = (i & 31) * 4;
        float4 v = *reinterpret_cast<const float4*>(g_A1 + kk * 2304 + oj0 * 16 + c4);
        *reinterpret_cast<float4*>(wT + kk * 132 + c4) = v;
    }
    __syncthreads();

    ull acc[8][4];
    #pragma unroll
    for (int i = 0; i < 8; i++)
        #pragma unroll
        for (int p = 0; p < 4; p++) acc[i][p] = 0ull;

    const float* pa = aT + rg;
    const float* pw = wT + 8 * cg;
    #pragma unroll 2
    for (int k = 0; k < 96; k++) {
        ull wv[4];
        #pragma unroll
        for (int p = 0; p < 4; p++)
            wv[p] = *reinterpret_cast<const ull*>(pw + k * 132 + 2 * p);
        ull ad[8];
        #pragma unroll
        for (int i = 0; i < 8; i++) ad[i] = dup2(pa[k * 129 + 16 * i]);
        #pragma unroll
        for (int i = 0; i < 8; i++)
            #pragma unroll
            for (int p = 0; p < 4; p++) fma2(acc[i][p], ad[i], wv[p]);
    }
    __syncthreads();

    // pre[128][130] reuses smem
    float* pre = sm;
    #pragma unroll
    for (int i = 0; i < 8; i++)
        #pragma unroll
        for (int p = 0; p < 4; p++)
            *reinterpret_cast<float2*>(pre + (rg + 16 * i) * 130 + 8 * cg + 2 * p) =
                *reinterpret_cast<float2*>(&acc[i][p]);
    __syncthreads();

    // Pool(4,s2,p1)+relu+stats. thread = (row, half) -> 4 oj groups. Stores to
    // transposed g_t1[kidx][b] (coalesced across row-threads).
    const int row = t & 127, half = t >> 7;
    const float* pr = pre + row * 130;
    #pragma unroll
    for (int gg = 0; gg < 4; gg++) {
        int g = half * 4 + gg;
        int oj = oj0 + g;
        int o = oj / 9, jj = oj - o * 9;
        float* dst = g_t1 + (long)(o * 72 + jj * 8) * 4096 + b0 + row;
        float s = 0.f, ss = 0.f;
        #pragma unroll
        for (int k = 0; k < 8; k++) {
            int lo = (2 * k - 1 < 0) ? 0 : 2 * k - 1;
            int hi = (2 * k + 2 > 15) ? 15 : 2 * k + 2;
            float m = pr[g * 16 + lo];
            for (int nn = lo + 1; nn <= hi; nn++) m = fmaxf(m, pr[g * 16 + nn]);
            m = fmaxf(m, 0.f);
            dst[k * 4096] = m;
            s += m; ss += m * m;
        }
        float sA = warp_sum(s), ssA = warp_sum(ss);
        if ((t & 31) == 0) {
            atomicAdd(&g_red[o], sA);
            atomicAdd(&g_red[16 + o], ssA);
        }
    }
}

// BN params for layer1 only.
__global__ void k_bn1(const float* __restrict__ g, const float* __restrict__ b) {
    int c = threadIdx.x;
    if (c >= 16) return;
    float sum = g_red[c], ssq = g_red[16 + c];
    float mean = sum / 294912.f;
    float var = ssq / 294912.f - mean * mean;
    float sc = g[c] * rsqrtf(var + 2e-5f);
    g_bn1[c] = sc;
    g_bn1[16 + c] = b[c] - mean * sc;
}

// Fused: bias2 accumulation (from unscaled A2) + in-place BN1 scaling of A2.
__global__ void k_biasscale2() {
    int id = blockIdx.x * blockDim.x + threadIdx.x;
    if (id >= 14336) return;
    int j = id >> 11, rem = id & 2047;
    int col = rem & 255, gg = rem >> 8;          // gg 0..7 -> kk gg*48..+47, c = 2gg, 2gg+1
    float sc0 = g_bn1[2 * gg],     sh0 = g_bn1[16 + 2 * gg];
    float sc1 = g_bn1[2 * gg + 1], sh1 = g_bn1[16 + 2 * gg + 1];
    float* base = g_A2 + (long)j * 98304 + (long)gg * 48 * 256 + col;
    float s = 0.f;
    #pragma unroll 4
    for (int kkl = 0; kkl < 24; kkl++) {
        float v = base[kkl * 256];
        s += sh0 * v;
        base[kkl * 256] = v * sc0;
    }
    #pragma unroll 4
    for (int kkl = 24; kkl < 48; kkl++) {
        float v = base[kkl * 256];
        s += sh1 * v;
        base[kkl * 256] = v * sc1;
    }
    atomicAdd(&g_bias2[j * 256 + col], s);
}

// ---------------------------------------------------------------------------
// Layer2: per j: C[4096 x 256] = acts[4096 x 384] * A2'[j] + bias2[j],
// fused pool+relu+stats. BN1 pre-folded -> staging pure vectorized copies.
// Block 128 rows x 128 cols, 256 thr, col-pair FMA2. K in 6 tiles of 64.
// smem 67584 B. 2 blocks/SM (NO reg-cap: acc file is 64 regs).
// ---------------------------------------------------------------------------
__global__ void __launch_bounds__(256, 2) k_layer2() {
    extern __shared__ float sm[];
    float* aT = sm;               // [64][132]
    float* wT = sm + 8448;        // [64][132]
    const int t = threadIdx.x;
    const int b0 = blockIdx.x * 128;
    const int cb = blockIdx.y;    // col block: o2 channels cb*16..+15
    const int j  = blockIdx.z;
    const int rg = t & 15, cg = t >> 4;

    ull acc[8][4];
    #pragma unroll
    for (int i = 0; i < 8; i++)
        #pragma unroll
        for (int p = 0; p < 4; p++) acc[i][p] = 0ull;

    const float* wbase = g_A2 + j * 98304 + cb * 128;

    for (int kt = 0; kt < 6; kt++) {
        __syncthreads();
        // acts tile: pure float4 copy from transposed g_t1
        for (int i = t; i < 2048; i += 256) {
            int kk = i >> 5, r4 = (i & 31) * 4;
            int k = kt * 64 + kk;
            int c = k / 24, rem = k - c * 24;
            float4 v = *reinterpret_cast<const float4*>(
                g_t1 + (long)(c * 72 + j * 8 + rem) * 4096 + b0 + r4);
            *reinterpret_cast<float4*>(aT + kk * 132 + r4) = v;
        }
        // weight tile: float4 copy
        for (int i = t; i < 2048; i += 256) {
            int kk = i >> 5, c4 = (i & 31) * 4;
            float4 v = *reinterpret_cast<const float4*>(wbase + (kt * 64 + kk) * 256 + c4);
            *reinterpret_cast<float4*>(wT + kk * 132 + c4) = v;
        }
        __syncthreads();

        const float* pa = aT + rg;
        const float* pw = wT + 8 * cg;
        #pragma unroll 2
        for (int k = 0; k < 64; k++) {
            ull wv[4];
            #pragma unroll
            for (int p = 0; p < 4; p++)
                wv[p] = *reinterpret_cast<const ull*>(pw + k * 132 + 2 * p);
            ull ad[8];
            #pragma unroll
            for (int i = 0; i < 8; i++) ad[i] = dup2(pa[k * 132 + 16 * i]);
            #pragma unroll
            for (int i = 0; i < 8; i++)
                #pragma unroll
                for (int p = 0; p < 4; p++) fma2(acc[i][p], ad[i], wv[p]);
        }
    }
    __syncthreads();

    // add bias2 and spill to pre[128][130]
    float* pre = sm;
    {
        const float* bb = g_bias2 + j * 256 + cb * 128 + 8 * cg;
        float2 bv[4];
        #pragma unroll
        for (int p = 0; p < 4; p++) bv[p] = *reinterpret_cast<const float2*>(bb + 2 * p);
        __syncthreads();
        #pragma unroll
        for (int i = 0; i < 8; i++)
            #pragma unroll
            for (int p = 0; p < 4; p++) {
                float2 v = *reinterpret_cast<float2*>(&acc[i][p]);
                v.x += bv[p].x; v.y += bv[p].y;
                *reinterpret_cast<float2*>(pre + (rg + 16 * i) * 130 + 8 * cg + 2 * p) = v;
            }
    }
    __syncthreads();

    // Pool(4,s2,p1)+relu+stats -> transposed g_t2[idx][b]
    const int row = t & 127, half = t >> 7;
    const float* pr = pre + row * 130;
    #pragma unroll
    for (int ol = 0; ol < 8; ol++) {
        int lc = half * 8 + ol;
        int o2g = cb * 16 + lc;
        float* dst = g_t2 + (long)(o2g * 28 + j * 4) * 4096 + b0 + row;
        float s = 0.f, ss = 0.f;
        #pragma unroll
        for (int k = 0; k < 4; k++) {
            int lo = (2 * k - 1 < 0) ? 0 : 2 * k - 1;
            int hi = (2 * k + 2 > 7) ? 7 : 2 * k + 2;
            float m = pr[lc * 8 + lo];
            for (int nn = lo + 1; nn <= hi; nn++) m = fmaxf(m, pr[lc * 8 + nn]);
            m = fmaxf(m, 0.f);
            dst[k * 4096] = m;
            s += m; ss += m * m;
        }
        float sA = warp_sum(s), ssA = warp_sum(ss);
        if ((t & 31) == 0) {
            atomicAdd(&g_red[32 + o2g], sA);
            atomicAdd(&g_red[64 + o2g], ssA);
        }
    }
}

// Fused: BN2 params + fold into w3 (g_w3f) and bias3. Single block.
__global__ void k_bnfold2(const float* __restrict__ g, const float* __restrict__ b,
                          const float* __restrict__ w3) {
    int t = threadIdx.x;
    if (t < 32) {
        float sum = g_red[32 + t], ssq = g_red[64 + t];
        float mean = sum / 114688.f;
        float var = ssq / 114688.f - mean * mean;
        float sc = g[t] * rsqrtf(var + 2e-5f);
        g_bn2[t] = sc;
        g_bn2[32 + t] = b[t] - mean * sc;
    }
    __syncthreads();
    for (int i = t; i < 6144; i += 256) {
        int kidx = i >> 6, o = i & 63;
        int c = kidx / 3, rr = kidx - c * 3;
        g_w3f[i] = w3[(o * 32 + c) * 3 + rr] * g_bn2[c];
    }
    if (t < 64) {
        float s = 0.f;
        for (int c = 0; c < 32; c++)
            s += (w3[(t * 32 + c) * 3] + w3[(t * 32 + c) * 3 + 1] + w3[(t * 32 + c) * 3 + 2])
                 * g_bn2[32 + c];
        g_bias3[t] = s;
    }
}

// ---------------------------------------------------------------------------
// Layer3: per batch-tile of 16 rows, f32x2 row-pair. smem 96256 B, 2 blk/SM.
// ---------------------------------------------------------------------------
__global__ void __launch_bounds__(256, 2) k_layer3() {
    extern __shared__ float sm[];
    float* actsT = sm;             // [896][20]
    float* ws    = sm + 17920;     // [96][64]
    __shared__ float st[128];
    const int t = threadIdx.x;
    const int b0 = blockIdx.x * 16;

    for (int i = t; i < 3584; i += 256) {
        int idx = i >> 2, r4 = (i & 3) * 4;
        float4 v = *reinterpret_cast<const float4*>(g_t2 + (long)idx * 4096 + b0 + r4);
        *reinterpret_cast<float4*>(actsT + idx * 20 + r4) = v;
    }
    for (int i = t; i < 6144; i += 256) ws[i] = g_w3f[i];
    if (t < 128) st[t] = 0.f;
    __syncthreads();

    const int o3 = t & 63, rpg = t >> 6;
    const ull* a64 = reinterpret_cast<const ull*>(actsT);  // stride 10 per idx
    const float invj[5] = {1.f, 0.5f, 0.25f, 0.125f, 0.0625f};
    const float bias = g_bias3[o3];
    float s = 0.f, ssq = 0.f;

    #pragma unroll
    for (int hf = 0; hf < 2; hf++) {
        const int rp = rpg + 4 * hf;
        ull accp[15];
        #pragma unroll
        for (int i = 0; i < 15; i++) accp[i] = 0ull;

        for (int c = 0; c < 32; c++) {
            ull av[21];
            #pragma unroll
            for (int m = 0; m < 7; m++)
                #pragma unroll
                for (int l = 0; l < 3; l++)
                    av[m * 3 + l] = a64[(c * 28 + m * 4 + l) * 10 + rp];
            ull w0 = dup2(ws[(c * 3 + 0) * 64 + o3]);
            ull w1 = dup2(ws[(c * 3 + 1) * 64 + o3]);
            ull w2 = dup2(ws[(c * 3 + 2) * 64 + o3]);
            #pragma unroll
            for (int jj = 0; jj < 5; jj++)
                #pragma unroll
                for (int l = 0; l < 3; l++) {
                    fma2(accp[jj * 3 + l], w0, av[(jj + 0) * 3 + l]);
                    fma2(accp[jj * 3 + l], w1, av[(jj + 1) * 3 + l]);
                    fma2(accp[jj * 3 + l], w2, av[(jj + 2) * 3 + l]);
                }
        }
        #pragma unroll
        for (int jj = 0; jj < 5; jj++) {
            float2 v0 = *reinterpret_cast<float2*>(&accp[jj * 3 + 0]);
            float2 v1 = *reinterpret_cast<float2*>(&accp[jj * 3 + 1]);
            float2 v2 = *reinterpret_cast<float2*>(&accp[jj * 3 + 2]);
            float mx = (fmaxf(fmaxf(v0.x, v1.x), v2.x) + bias) * invj[jj];
            float my = (fmaxf(fmaxf(v0.y, v1.y), v2.y) + bias) * invj[jj];
            mx = fmaxf(mx, 0.f); my = fmaxf(my, 0.f);
            *reinterpret_cast<float2*>(g_t3 + (long)(o3 * 5 + jj) * 4096 + b0 + 2 * rp) =
                make_float2(mx, my);
            s += mx + my; ssq += mx * mx + my * my;
        }
    }
    atomicAdd(&st[o3], s);
    atomicAdd(&st[64 + o3], ssq);
    __syncthreads();
    if (t < 64) { atomicAdd(&g_red[96 + t], st[t]); atomicAdd(&g_red[160 + t], st[64 + t]); }
}

// Fused: BN3 params + fold into fw1 (g_fw1f/g_fb1f). Single block.
__global__ void k_bnfold3(const float* __restrict__ g, const float* __restrict__ b,
                          const float* __restrict__ fw1, const float* __restrict__ fb1) {
    int t = threadIdx.x;
    if (t < 64) {
        float sum = g_red[96 + t], ssq = g_red[160 + t];
        float mean = sum / 20480.f;
        float var = ssq / 20480.f - mean * mean;
        float sc = g[t] * rsqrtf(var + 2e-5f);
        g_bn3[t] = sc;
        g_bn3[64 + t] = b[t] - mean * sc;
    }
    __syncthreads();
    for (int i = t; i < 5120; i += 256) {
        int o = i / 320, k = i - o * 320;
        g_fw1f[k * 16 + o] = fw1[i] * g_bn3[k / 5];
    }
    if (t < 16) {
        float s = fb1[t];
        for (int k = 0; k < 320; k++)
            s += fw1[t * 320 + k] * g_bn3[64 + k / 5];
        g_fb1f[t] = s;
    }
}

// 3-layer MLP; BN3 prefolded into g_fw1f/g_fb1f; t3 transposed staging.
__global__ void __launch_bounds__(128) k_fc(const float* __restrict__ fw2, const float* __restrict__ fb2,
                                            const float* __restrict__ fw3, const float* __restrict__ fb3,
                                            float* __restrict__ out) {
    __shared__ float w1s[5120];            // [k][o]
    __shared__ float vtT[32 * 132];        // [c2][row]
    __shared__ float w2s[256];
    __shared__ float w3s[272];
    __shared__ float b1s[16], b2s[16], b3s[17];
    int t = threadIdx.x;
    int bbase = blockIdx.x * 128;
    for (int i = t; i < 5120; i += 128) w1s[i] = g_fw1f[i];
    for (int i = t; i < 256; i += 128) w2s[i] = fw2[i];
    for (int i = t; i < 272; i += 128) w3s[i] = fw3[i];
    if (t < 16) { b1s[t] = g_fb1f[t]; b2s[t] = fb2[t]; }
    if (t < 17) b3s[t] = fb3[t];
    __syncthreads();

    float h1[16];
    #pragma unroll
    for (int o = 0; o < 16; o++) h1[o] = b1s[o];

    for (int i0 = 0; i0 < 320; i0 += 32) {
        __syncthreads();
        for (int i = t; i < 1024; i += 128) {
            int c2 = i >> 5, r4 = (i & 31) * 4;
            float4 v = *reinterpret_cast<const float4*>(g_t3 + (long)(i0 + c2) * 4096 + bbase + r4);
            *reinterpret_cast<float4*>(vtT + c2 * 132 + r4) = v;
        }
        __syncthreads();
        #pragma unroll 4
        for (int c2 = 0; c2 < 32; c2++) {
            float v = vtT[c2 * 132 + t];
            const float* wr = &w1s[(i0 + c2) * 16];
            #pragma unroll
            for (int o = 0; o < 16; o++) h1[o] += v * wr[o];
        }
    }
    float h2[16];
    #pragma unroll
    for (int o = 0; o < 16; o++) {
        float a = b2s[o];
        #pragma unroll
        for (int k = 0; k < 16; k++) a += h1[k] * w2s[o * 16 + k];
        h2[o] = a;
    }
    int b = bbase + t;
    #pragma unroll
    for (int o = 0; o < 17; o++) {
        float a = b3s[o];
        #pragma unroll
        for (int k = 0; k < 16; k++) a += h2[k] * w3s[o * 16 + k];
        out[b * 17 + o] = a;
    }
}

extern "C" void kernel_launch(void* const* d_in, const int* in_sizes, int n_in,
                              void* d_out, int out_size) {
    const float* x   = (const float*)d_in[0];
    const float* w1  = (const float*)d_in[1];
    const float* w2  = (const float*)d_in[2];
    const float* w3  = (const float*)d_in[3];
    const float* g1  = (const float*)d_in[4];
    const float* b1  = (const float*)d_in[5];
    const float* g2  = (const float*)d_in[6];
    const float* b2  = (const float*)d_in[7];
    const float* g3  = (const float*)d_in[8];
    const float* b3  = (const float*)d_in[9];
    const float* fw1 = (const float*)d_in[10];
    const float* fb1 = (const float*)d_in[11];
    const float* fw2 = (const float*)d_in[12];
    const float* fb2 = (const float*)d_in[13];
    const float* fw3 = (const float*)d_in[14];
    const float* fb3 = (const float*)d_in[15];
    float* out = (float*)d_out;

    cudaFuncSetAttribute(k_layer1, cudaFuncAttributeMaxDynamicSharedMemorySize, 100224);
    cudaFuncSetAttribute(k_layer2, cudaFuncAttributeMaxDynamicSharedMemorySize, 67584);
    cudaFuncSetAttribute(k_layer3, cudaFuncAttributeMaxDynamicSharedMemorySize, 96256);

    k_prep<<<2688, 256>>>(w1, w2);
    k_layer1<<<dim3(32, 18), 256, 100224>>>(x);
    k_bn1<<<1, 32>>>(g1, b1);
    k_biasscale2<<<56, 256>>>();
    k_layer2<<<dim3(32, 2, 7), 256, 67584>>>();
    k_bnfold2<<<1, 256>>>(g2, b2, w3);
    k_layer3<<<256, 256, 96256>>>();
    k_bnfold3<<<1, 256>>>(g3, b3, fw1, fb1);
    k_fc<<<32, 128>>>(fw2, fb2, fw3, fb3, out);
}

// round 17
// speedup vs baseline: 2.0224x; 1.0157x over previous
#include <cuda_runtime.h>

// ---------------- scratch (device globals; no allocation allowed) ----------------
__device__ float g_A1[221184];    // layer1 eff weights, k-major: [kk(96)][ojcol(2304)=oj*16+n]
__device__ float g_A2[688128];    // layer2 eff weights: [j][kk(384)][col(256)] (UNscaled)
__device__ float g_s2[28672];     // channel-sums of A2: [j(7)][c(16)][col(256)]
__device__ float g_t1[4718592];   // transposed: [kidx(1152)=c*72+j*8+n][b(4096)]
__device__ float g_t2[3670016];   // transposed: [idx(896)=c*28+j*4+l][b(4096)]
__device__ float g_t3[1310720];   // transposed: [idx(320)=o*5+j][b(4096)]
__device__ float g_red[224];      // sum1[16] ssq1[16] sum2[32] ssq2[32] sum3[64] ssq3[64]
__device__ float g_bn1[32];       // [scale16][shift16]
__device__ float g_bn2[64];       // [scale32][shift32]
__device__ float g_bn3[128];      // [scale64][shift64]
__device__ float g_bias2[1792];   // [j(7)][col(256)]  BN1-shift folded through A2
__device__ float g_w3f[6144];     // [kidx(96)=c*3+rr][o3(64)]  BN2-scale folded
__device__ float g_bias3[64];     // BN2-shift folded through w3
__device__ float g_fw1f[5120];    // transposed [k(320)][o(16)], BN3-scale folded
__device__ float g_fb1f[16];      // BN3-shift folded

typedef unsigned long long ull;

__device__ __forceinline__ void fma2(ull& d, ull a, ull b) {
    asm("fma.rn.f32x2 %0, %1, %2, %0;" : "+l"(d) : "l"(a), "l"(b));
}
__device__ __forceinline__ ull dup2(float v) {
    ull r;
    asm("mov.b64 %0, {%1, %1};" : "=l"(r) : "f"(v));
    return r;
}
__device__ __forceinline__ float warp_sum(float v) {
    #pragma unroll
    for (int o = 16; o; o >>= 1) v += __shfl_down_sync(0xffffffffu, v, o);
    return v;
}

// Combined prep: zero reductions, build A1 (k-major), A2 (fp32, unscaled),
// and the BN-independent channel-sums g_s2 (analytic clipped-hat row sums).
__global__ void k_prep(const float* __restrict__ w1, const float* __restrict__ w2) {
    int id = blockIdx.x * blockDim.x + threadIdx.x;
    if (id < 224) g_red[id] = 0.f;
    if (id < 221184) {
        int n  = id & 15;
        int kk = (id >> 4) % 96;
        int oj = id / 1536;
        int o = oj / 9, j = oj % 9;
        int c = kk >> 4, p = kk & 15;
        int h = 1 << j;
        int d = p - n;
        float v = 0.f;
        if (d >= -3 * h && d <= 3 * h) {
            float t = (float)d / (float)h;
            #pragma unroll
            for (int mm = 0; mm < 7; mm++) {
                float hat = 1.f - fabsf(t - (float)(mm - 3));
                if (hat > 0.f) v += w1[(o * 6 + c) * 7 + mm] * hat;
            }
            v /= (float)h;
        }
        g_A1[kk * 2304 + oj * 16 + n] = v;
    }
    if (id < 688128) {
        int col = id & 255;
        int kk  = (id >> 8) % 384;
        int j   = id / 98304;
        int o = col >> 3, n = col & 7;
        int p = kk & 7;
        int cr = kk >> 3;               // c*3+r
        int h = 1 << j;
        int d = p - n;
        float v = 0.f;
        if (d >= -h && d <= h) {
            float t = (float)d / (float)h;
            #pragma unroll
            for (int mm = 0; mm < 3; mm++) {
                float hat = 1.f - fabsf(t - (float)(mm - 1));
                if (hat > 0.f) v += w2[(o * 48 + cr) * 3 + mm] * hat;
            }
            v /= (float)h;
        }
        g_A2[id] = v;
    }
    if (id < 28672) {
        // S[j][c][col] = sum over the 24 kk in channel c of A2[j][kk][col]
        //             = sum_r sum_m w2[o,c,r,m] * T[j][n][m],
        // T[j][n][m] = (1/h) * sum_{p: |p-n|<=h} hat((p-n)/h - (m-1))
        int j = id / 4096, rem = id - j * 4096;
        int c = rem >> 8, col = rem & 255;
        int o = col >> 3, n = col & 7;
        int h = 1 << j;
        float invh = 1.f / (float)h;
        float T[3];
        #pragma unroll
        for (int m = 0; m < 3; m++) {
            float tacc = 0.f;
            #pragma unroll
            for (int p = 0; p < 8; p++) {
                int d = p - n;
                if (d >= -h && d <= h) {
                    float hat = 1.f - fabsf((float)d * invh - (float)(m - 1));
                    if (hat > 0.f) tacc += hat;
                }
            }
            T[m] = tacc * invh;
        }
        float s = 0.f;
        #pragma unroll
        for (int r = 0; r < 3; r++)
            #pragma unroll
            for (int m = 0; m < 3; m++)
                s += w2[(o * 48 + c * 3 + r) * 3 + m] * T[m];
        g_s2[id] = s;
    }
}

// ---------------------------------------------------------------------------
// Layer1: C[4096 x 2304] = X[4096 x 96] * A1[96 x 2304], fused pool+relu+stats.
// Block 128 rows x 128 cols (8 oj groups), 256 threads, col-pair FMA2.
// smem: aT[96][129]=12384 | wT[96][132]=12672 floats => 100224 B. 2 blk/SM.
// ---------------------------------------------------------------------------
__global__ void __launch_bounds__(256, 2) k_layer1(const float* __restrict__ x) {
    extern __shared__ float sm[];
    float* aT = sm;               // [96][129]
    float* wT = sm + 12384;       // [96][132]
    const int t = threadIdx.x;
    const int b0  = blockIdx.x * 128;
    const int oj0 = blockIdx.y * 8;
    const int rg = t & 15, cg = t >> 4;

    // stage X transposed (scalar: LDG coalesced, STS stride-129 conflict-free)
    for (int i = t; i < 12288; i += 256) {
        int r = i / 96, kk = i - r * 96;
        aT[kk * 129 + r] = x[(b0 + r) * 96 + kk];
    }
    // stage W vectorized (A1 k-major, contiguous 128 floats per kk)
    for (int i = t; i < 3072; i += 256) {
        int kk = i >> 5, c4 = (i & 31) * 4;
        float4 v = *reinterpret_cast<const float4*>(g_A1 + kk * 2304 + oj0 * 16 + c4);
        *reinterpret_cast<float4*>(wT + kk * 132 + c4) = v;
    }
    __syncthreads();

    ull acc[8][4];
    #pragma unroll
    for (int i = 0; i < 8; i++)
        #pragma unroll
        for (int p = 0; p < 4; p++) acc[i][p] = 0ull;

    const float* pa = aT + rg;
    const float* pw = wT + 8 * cg;
    #pragma unroll 2
    for (int k = 0; k < 96; k++) {
        ull wv[4];
        #pragma unroll
        for (int p = 0; p < 4; p++)
            wv[p] = *reinterpret_cast<const ull*>(pw + k * 132 + 2 * p);
        ull ad[8];
        #pragma unroll
        for (int i = 0; i < 8; i++) ad[i] = dup2(pa[k * 129 + 16 * i]);
        #pragma unroll
        for (int i = 0; i < 8; i++)
            #pragma unroll
            for (int p = 0; p < 4; p++) fma2(acc[i][p], ad[i], wv[p]);
    }
    __syncthreads();

    // pre[128][130] reuses smem
    float* pre = sm;
    #pragma unroll
    for (int i = 0; i < 8; i++)
        #pragma unroll
        for (int p = 0; p < 4; p++)
            *reinterpret_cast<float2*>(pre + (rg + 16 * i) * 130 + 8 * cg + 2 * p) =
                *reinterpret_cast<float2*>(&acc[i][p]);
    __syncthreads();

    // Pool(4,s2,p1)+relu+stats -> transposed g_t1[kidx][b]
    const int row = t & 127, half = t >> 7;
    const float* pr = pre + row * 130;
    #pragma unroll
    for (int gg = 0; gg < 4; gg++) {
        int g = half * 4 + gg;
        int oj = oj0 + g;
        int o = oj / 9, jj = oj - o * 9;
        float* dst = g_t1 + (long)(o * 72 + jj * 8) * 4096 + b0 + row;
        float s = 0.f, ss = 0.f;
        #pragma unroll
        for (int k = 0; k < 8; k++) {
            int lo = (2 * k - 1 < 0) ? 0 : 2 * k - 1;
            int hi = (2 * k + 2 > 15) ? 15 : 2 * k + 2;
            float m = pr[g * 16 + lo];
            for (int nn = lo + 1; nn <= hi; nn++) m = fmaxf(m, pr[g * 16 + nn]);
            m = fmaxf(m, 0.f);
            dst[k * 4096] = m;
            s += m; ss += m * m;
        }
        float sA = warp_sum(s), ssA = warp_sum(ss);
        if ((t & 31) == 0) {
            atomicAdd(&g_red[o], sA);
            atomicAdd(&g_red[16 + o], ssA);
        }
    }
}

// BN1 params + bias2 (from precomputed g_s2). 7 blocks x 256 = 1792 threads;
// every block redundantly computes bn1 into smem (block 0 publishes g_bn1).
__global__ void k_bn1x(const float* __restrict__ g, const float* __restrict__ b) {
    __shared__ float sh[32];
    int t = threadIdx.x;
    if (t < 16) {
        float sum = g_red[t], ssq = g_red[16 + t];
        float mean = sum / 294912.f;
        float var = ssq / 294912.f - mean * mean;
        float sc = g[t] * rsqrtf(var + 2e-5f);
        float shf = b[t] - mean * sc;
        sh[t] = sc; sh[16 + t] = shf;
        if (blockIdx.x == 0) { g_bn1[t] = sc; g_bn1[16 + t] = shf; }
    }
    __syncthreads();
    int id = blockIdx.x * 256 + t;   // 0..1791
    int j = id >> 8, col = id & 255;
    float s = 0.f;
    #pragma unroll
    for (int c = 0; c < 16; c++)
        s += sh[16 + c] * g_s2[(j * 16 + c) * 256 + col];
    g_bias2[id] = s;
}

// ---------------------------------------------------------------------------
// Layer2: per j: C[4096 x 256] = acts[4096 x 384] * (A2[j]*sc1) + bias2[j].
// BN1 scale folded into weight staging. Block 128 x 128, 256 thr, col-pair
// FMA2. K in 4 tiles of 96. smem 101376 B, 2 blocks/SM.
// ---------------------------------------------------------------------------
__global__ void __launch_bounds__(256, 2) k_layer2() {
    extern __shared__ float sm[];
    __shared__ float bnS[32];
    float* aT = sm;               // [96][132]
    float* wT = sm + 12672;       // [96][132]
    const int t = threadIdx.x;
    const int b0 = blockIdx.x * 128;
    const int cb = blockIdx.y;    // col block: o2 channels cb*16..+15
    const int j  = blockIdx.z;
    const int rg = t & 15, cg = t >> 4;

    if (t < 32) bnS[t] = g_bn1[t];

    ull acc[8][4];
    #pragma unroll
    for (int i = 0; i < 8; i++)
        #pragma unroll
        for (int p = 0; p < 4; p++) acc[i][p] = 0ull;

    const float* wbase = g_A2 + j * 98304 + cb * 128;

    for (int kt = 0; kt < 4; kt++) {
        __syncthreads();
        // acts tile: pure float4 copy from transposed g_t1
        for (int i = t; i < 3072; i += 256) {
            int kk = i >> 5, r4 = (i & 31) * 4;
            int k = kt * 96 + kk;
            int c = k / 24, rem = k - c * 24;
            float4 v = *reinterpret_cast<const float4*>(
                g_t1 + (long)(c * 72 + j * 8 + rem) * 4096 + b0 + r4);
            *reinterpret_cast<float4*>(aT + kk * 132 + r4) = v;
        }
        // weight tile: float4 copy with BN1 scale folded in
        for (int i = t; i < 3072; i += 256) {
            int kk = i >> 5, c4 = (i & 31) * 4;
            int k = kt * 96 + kk;
            float sc = bnS[k / 24];
            float4 v = *reinterpret_cast<const float4*>(wbase + (long)k * 256 + c4);
            v.x *= sc; v.y *= sc; v.z *= sc; v.w *= sc;
            *reinterpret_cast<float4*>(wT + kk * 132 + c4) = v;
        }
        __syncthreads();

        const float* pa = aT + rg;
        const float* pw = wT + 8 * cg;
        #pragma unroll 2
        for (int k = 0; k < 96; k++) {
            ull wv[4];
            #pragma unroll
            for (int p = 0; p < 4; p++)
                wv[p] = *reinterpret_cast<const ull*>(pw + k * 132 + 2 * p);
            ull ad[8];
            #pragma unroll
            for (int i = 0; i < 8; i++) ad[i] = dup2(pa[k * 132 + 16 * i]);
            #pragma unroll
            for (int i = 0; i < 8; i++)
                #pragma unroll
                for (int p = 0; p < 4; p++) fma2(acc[i][p], ad[i], wv[p]);
        }
    }
    __syncthreads();

    // add bias2 and spill to pre[128][130]
    float* pre = sm;
    {
        const float* bb = g_bias2 + j * 256 + cb * 128 + 8 * cg;
        float2 bv[4];
        #pragma unroll
        for (int p = 0; p < 4; p++) bv[p] = *reinterpret_cast<const float2*>(bb + 2 * p);
        __syncthreads();
        #pragma unroll
        for (int i = 0; i < 8; i++)
            #pragma unroll
            for (int p = 0; p < 4; p++) {
                float2 v = *reinterpret_cast<float2*>(&acc[i][p]);
                v.x += bv[p].x; v.y += bv[p].y;
                *reinterpret_cast<float2*>(pre + (rg + 16 * i) * 130 + 8 * cg + 2 * p) = v;
            }
    }
    __syncthreads();

    // Pool(4,s2,p1)+relu+stats -> transposed g_t2[idx][b]
    const int row = t & 127, half = t >> 7;
    const float* pr = pre + row * 130;
    #pragma unroll
    for (int ol = 0; ol < 8; ol++) {
        int lc = half * 8 + ol;
        int o2g = cb * 16 + lc;
        float* dst = g_t2 + (long)(o2g * 28 + j * 4) * 4096 + b0 + row;
        float s = 0.f, ss = 0.f;
        #pragma unroll
        for (int k = 0; k < 4; k++) {
            int lo = (2 * k - 1 < 0) ? 0 : 2 * k - 1;
            int hi = (2 * k + 2 > 7) ? 7 : 2 * k + 2;
            float m = pr[lc * 8 + lo];
            for (int nn = lo + 1; nn <= hi; nn++) m = fmaxf(m, pr[lc * 8 + nn]);
            m = fmaxf(m, 0.f);
            dst[k * 4096] = m;
            s += m; ss += m * m;
        }
        float sA = warp_sum(s), ssA = warp_sum(ss);
        if ((t & 31) == 0) {
            atomicAdd(&g_red[32 + o2g], sA);
            atomicAdd(&g_red[64 + o2g], ssA);
        }
    }
}

// Fused: BN2 params + fold into w3 (g_w3f) and bias3. Single block.
__global__ void k_bnfold2(const float* __restrict__ g, const float* __restrict__ b,
                          const float* __restrict__ w3) {
    int t = threadIdx.x;
    if (t < 32) {
        float sum = g_red[32 + t], ssq = g_red[64 + t];
        float mean = sum / 114688.f;
        float var = ssq / 114688.f - mean * mean;
        float sc = g[t] * rsqrtf(var + 2e-5f);
        g_bn2[t] = sc;
        g_bn2[32 + t] = b[t] - mean * sc;
    }
    __syncthreads();
    for (int i = t; i < 6144; i += 256) {
        int kidx = i >> 6, o = i & 63;
        int c = kidx / 3, rr = kidx - c * 3;
        g_w3f[i] = w3[(o * 32 + c) * 3 + rr] * g_bn2[c];
    }
    if (t < 64) {
        float s = 0.f;
        for (int c = 0; c < 32; c++)
            s += (w3[(t * 32 + c) * 3] + w3[(t * 32 + c) * 3 + 1] + w3[(t * 32 + c) * 3 + 2])
                 * g_bn2[32 + c];
        g_bias3[t] = s;
    }
}

// ---------------------------------------------------------------------------
// Layer3: per batch-tile of 16 rows, f32x2 row-pair. smem 96256 B, 2 blk/SM.
// ---------------------------------------------------------------------------
__global__ void __launch_bounds__(256, 2) k_layer3() {
    extern __shared__ float sm[];
    float* actsT = sm;             // [896][20]
    float* ws    = sm + 17920;     // [96][64]
    __shared__ float st[128];
    const int t = threadIdx.x;
    const int b0 = blockIdx.x * 16;

    for (int i = t; i < 3584; i += 256) {
        int idx = i >> 2, r4 = (i & 3) * 4;
        float4 v = *reinterpret_cast<const float4*>(g_t2 + (long)idx * 4096 + b0 + r4);
        *reinterpret_cast<float4*>(actsT + idx * 20 + r4) = v;
    }
    for (int i = t; i < 6144; i += 256) ws[i] = g_w3f[i];
    if (t < 128) st[t] = 0.f;
    __syncthreads();

    const int o3 = t & 63, rpg = t >> 6;
    const ull* a64 = reinterpret_cast<const ull*>(actsT);  // stride 10 per idx
    const float invj[5] = {1.f, 0.5f, 0.25f, 0.125f, 0.0625f};
    const float bias = g_bias3[o3];
    float s = 0.f, ssq = 0.f;

    #pragma unroll
    for (int hf = 0; hf < 2; hf++) {
        const int rp = rpg + 4 * hf;
        ull accp[15];
        #pragma unroll
        for (int i = 0; i < 15; i++) accp[i] = 0ull;

        for (int c = 0; c < 32; c++) {
            ull av[21];
            #pragma unroll
            for (int m = 0; m < 7; m++)
                #pragma unroll
                for (int l = 0; l < 3; l++)
                    av[m * 3 + l] = a64[(c * 28 + m * 4 + l) * 10 + rp];
            ull w0 = dup2(ws[(c * 3 + 0) * 64 + o3]);
            ull w1 = dup2(ws[(c * 3 + 1) * 64 + o3]);
            ull w2 = dup2(ws[(c * 3 + 2) * 64 + o3]);
            #pragma unroll
            for (int jj = 0; jj < 5; jj++)
                #pragma unroll
                for (int l = 0; l < 3; l++) {
                    fma2(accp[jj * 3 + l], w0, av[(jj + 0) * 3 + l]);
                    fma2(accp[jj * 3 + l], w1, av[(jj + 1) * 3 + l]);
                    fma2(accp[jj * 3 + l], w2, av[(jj + 2) * 3 + l]);
                }
        }
        #pragma unroll
        for (int jj = 0; jj < 5; jj++) {
            float2 v0 = *reinterpret_cast<float2*>(&accp[jj * 3 + 0]);
            float2 v1 = *reinterpret_cast<float2*>(&accp[jj * 3 + 1]);
            float2 v2 = *reinterpret_cast<float2*>(&accp[jj * 3 + 2]);
            float mx = (fmaxf(fmaxf(v0.x, v1.x), v2.x) + bias) * invj[jj];
            float my = (fmaxf(fmaxf(v0.y, v1.y), v2.y) + bias) * invj[jj];
            mx = fmaxf(mx, 0.f); my = fmaxf(my, 0.f);
            *reinterpret_cast<float2*>(g_t3 + (long)(o3 * 5 + jj) * 4096 + b0 + 2 * rp) =
                make_float2(mx, my);
            s += mx + my; ssq += mx * mx + my * my;
        }
    }
    atomicAdd(&st[o3], s);
    atomicAdd(&st[64 + o3], ssq);
    __syncthreads();
    if (t < 64) { atomicAdd(&g_red[96 + t], st[t]); atomicAdd(&g_red[160 + t], st[64 + t]); }
}

// Fused: BN3 params + fold into fw1 (g_fw1f/g_fb1f). Single block.
__global__ void k_bnfold3(const float* __restrict__ g, const float* __restrict__ b,
                          const float* __restrict__ fw1, const float* __restrict__ fb1) {
    int t = threadIdx.x;
    if (t < 64) {
        float sum = g_red[96 + t], ssq = g_red[160 + t];
        float mean = sum / 20480.f;
        float var = ssq / 20480.f - mean * mean;
        float sc = g[t] * rsqrtf(var + 2e-5f);
        g_bn3[t] = sc;
        g_bn3[64 + t] = b[t] - mean * sc;
    }
    __syncthreads();
    for (int i = t; i < 5120; i += 256) {
        int o = i / 320, k = i - o * 320;
        g_fw1f[k * 16 + o] = fw1[i] * g_bn3[k / 5];
    }
    if (t < 16) {
        float s = fb1[t];
        for (int k = 0; k < 320; k++)
            s += fw1[t * 320 + k] * g_bn3[64 + k / 5];
        g_fb1f[t] = s;
    }
}

// 3-layer MLP; BN3 prefolded into g_fw1f/g_fb1f; t3 transposed staging.
__global__ void __launch_bounds__(128) k_fc(const float* __restrict__ fw2, const float* __restrict__ fb2,
                                            const float* __restrict__ fw3, const float* __restrict__ fb3,
                                            float* __restrict__ out) {
    __shared__ float w1s[5120];            // [k][o]
    __shared__ float vtT[32 * 132];        // [c2][row]
    __shared__ float w2s[256];
    __shared__ float w3s[272];
    __shared__ float b1s[16], b2s[16], b3s[17];
    int t = threadIdx.x;
    int bbase = blockIdx.x * 128;
    for (int i = t; i < 5120; i += 128) w1s[i] = g_fw1f[i];
    for (int i = t; i < 256; i += 128) w2s[i] = fw2[i];
    for (int i = t; i < 272; i += 128) w3s[i] = fw3[i];
    if (t < 16) { b1s[t] = g_fb1f[t]; b2s[t] = fb2[t]; }
    if (t < 17) b3s[t] = fb3[t];
    __syncthreads();

    float h1[16];
    #pragma unroll
    for (int o = 0; o < 16; o++) h1[o] = b1s[o];

    for (int i0 = 0; i0 < 320; i0 += 32) {
        __syncthreads();
        for (int i = t; i < 1024; i += 128) {
            int c2 = i >> 5, r4 = (i & 31) * 4;
            float4 v = *reinterpret_cast<const float4*>(g_t3 + (long)(i0 + c2) * 4096 + bbase + r4);
            *reinterpret_cast<float4*>(vtT + c2 * 132 + r4) = v;
        }
        __syncthreads();
        #pragma unroll 4
        for (int c2 = 0; c2 < 32; c2++) {
            float v = vtT[c2 * 132 + t];
            const float* wr = &w1s[(i0 + c2) * 16];
            #pragma unroll
            for (int o = 0; o < 16; o++) h1[o] += v * wr[o];
        }
    }
    float h2[16];
    #pragma unroll
    for (int o = 0; o < 16; o++) {
        float a = b2s[o];
        #pragma unroll
        for (int k = 0; k < 16; k++) a += h1[k] * w2s[o * 16 + k];
        h2[o] = a;
    }
    int b = bbase + t;
    #pragma unroll
    for (int o = 0; o < 17; o++) {
        float a = b3s[o];
        #pragma unroll
        for (int k = 0; k < 16; k++) a += h2[k] * w3s[o * 16 + k];
        out[b * 17 + o] = a;
    }
}

extern "C" void kernel_launch(void* const* d_in, const int* in_sizes, int n_in,
                              void* d_out, int out_size) {
    const float* x   = (const float*)d_in[0];
    const float* w1  = (const float*)d_in[1];
    const float* w2  = (const float*)d_in[2];
    const float* w3  = (const float*)d_in[3];
    const float* g1  = (const float*)d_in[4];
    const float* b1  = (const float*)d_in[5];
    const float* g2  = (const float*)d_in[6];
    const float* b2  = (const float*)d_in[7];
    const float* g3  = (const float*)d_in[8];
    const float* b3  = (const float*)d_in[9];
    const float* fw1 = (const float*)d_in[10];
    const float* fb1 = (const float*)d_in[11];
    const float* fw2 = (const float*)d_in[12];
    const float* fb2 = (const float*)d_in[13];
    const float* fw3 = (const float*)d_in[14];
    const float* fb3 = (const float*)d_in[15];
    float* out = (float*)d_out;

    cudaFuncSetAttribute(k_layer1, cudaFuncAttributeMaxDynamicSharedMemorySize, 100224);
    cudaFuncSetAttribute(k_layer2, cudaFuncAttributeMaxDynamicSharedMemorySize, 101376);
    cudaFuncSetAttribute(k_layer3, cudaFuncAttributeMaxDynamicSharedMemorySize, 96256);

    k_prep<<<2688, 256>>>(w1, w2);
    k_layer1<<<dim3(32, 18), 256, 100224>>>(x);
    k_bn1x<<<7, 256>>>(g1, b1);
    k_layer2<<<dim3(32, 2, 7), 256, 101376>>>();
    k_bnfold2<<<1, 256>>>(g2, b2, w3);
    k_layer3<<<256, 256, 96256>>>();
    k_bnfold3<<<1, 256>>>(g3, b3, fw1, fb1);
    k_fc<<<32, 128>>>(fw2, fb2, fw3, fb3, out);
}